// round 5
// baseline (speedup 1.0000x reference)
#include <cuda_runtime.h>
#include <stdint.h>

// Problem constants
#define NUM_STEPS 25
#define BATCH     4096
#define NIN       784
#define NHID      1000
#define NOUT      10
#define MTOT      (NUM_STEPS * BATCH)   // 102400
#define BETA      0.95f
#define THRESH    1.0f

// Scratch (device globals; no runtime allocation allowed)
__device__ float    g_cur1[(size_t)MTOT * NHID];     // [t*B+b][h]
__device__ uint32_t g_maskT[(size_t)32 * MTOT];      // spk1 bits, [word][row]
__device__ float    g_cur2[(size_t)MTOT * NOUT];     // [t*B+b][o]

// ---------------------------------------------------------------------------
// Kernel 1: cur1 = X[102400,784] @ W1[1000,784]^T + b1
// Numerics hypothesis: reference = UNFUSED ascending chain (XLA:CPU, no FMA):
//   acc = rn(acc + rn(a_k * b_k)), k = 0..783, then one rn bias add.
// Implemented with __fmul_rn/__fadd_rn (contraction-proof intrinsics).
// Tile 128x128x16, 256 threads, 8x8 register tile.
// ---------------------------------------------------------------------------
#define BM 128
#define BN 128
#define BK 16
#define LDA (BM + 4)
#define LDB (BN + 4)

__global__ void __launch_bounds__(256, 2)
gemm1_kernel(const float* __restrict__ X, const float* __restrict__ W1,
             const float* __restrict__ b1)
{
    __shared__ float As[BK * LDA];
    __shared__ float Bs[BK * LDB];

    const int tid = threadIdx.x;
    const int bm  = blockIdx.y * BM;
    const int bn  = blockIdx.x * BN;

    // loader mapping: 256 threads load 128 rows x 16 cols as float4
    const int lr  = tid >> 2;          // 0..63
    const int lc4 = (tid & 3) * 4;     // 0,4,8,12

    // compute mapping
    const int tx   = tid & 15;
    const int ty   = tid >> 4;
    const int row0 = ty * 8;
    const int col0 = tx * 8;

    float acc[8][8];
#pragma unroll
    for (int i = 0; i < 8; i++)
#pragma unroll
        for (int j = 0; j < 8; j++) acc[i][j] = 0.f;

    for (int k0 = 0; k0 < NIN; k0 += BK) {
#pragma unroll
        for (int r = 0; r < 2; r++) {
            const int arow = lr + r * 64;
            // A tile (X): always in-bounds (M % 128 == 0, K % 16 == 0)
            float4 va = *(const float4*)(X + (size_t)(bm + arow) * NIN + k0 + lc4);
            As[(lc4 + 0) * LDA + arow] = va.x;
            As[(lc4 + 1) * LDA + arow] = va.y;
            As[(lc4 + 2) * LDA + arow] = va.z;
            As[(lc4 + 3) * LDA + arow] = va.w;
            // B tile (W1): guard n < 1000
            const int n = bn + arow;
            float4 vb = make_float4(0.f, 0.f, 0.f, 0.f);
            if (n < NHID)
                vb = *(const float4*)(W1 + (size_t)n * NIN + k0 + lc4);
            Bs[(lc4 + 0) * LDB + arow] = vb.x;
            Bs[(lc4 + 1) * LDB + arow] = vb.y;
            Bs[(lc4 + 2) * LDB + arow] = vb.z;
            Bs[(lc4 + 3) * LDB + arow] = vb.w;
        }
        __syncthreads();

#pragma unroll
        for (int k = 0; k < BK; k++) {   // ascending k; UNFUSED mul+add chain
            float a[8], b[8];
            *(float4*)(a)     = *(const float4*)&As[k * LDA + row0];
            *(float4*)(a + 4) = *(const float4*)&As[k * LDA + row0 + 4];
            *(float4*)(b)     = *(const float4*)&Bs[k * LDB + col0];
            *(float4*)(b + 4) = *(const float4*)&Bs[k * LDB + col0 + 4];
#pragma unroll
            for (int i = 0; i < 8; i++)
#pragma unroll
                for (int j = 0; j < 8; j++)
                    acc[i][j] = __fadd_rn(acc[i][j], __fmul_rn(a[i], b[j]));
        }
        __syncthreads();
    }

    // epilogue: single rn bias add, store cur1
#pragma unroll
    for (int i = 0; i < 8; i++) {
        const int m = bm + row0 + i;
#pragma unroll
        for (int j = 0; j < 8; j++) {
            const int n = bn + col0 + j;
            if (n < NHID)
                g_cur1[(size_t)m * NHID + n] = __fadd_rn(acc[i][j], __ldg(&b1[n]));
        }
    }
}

// ---------------------------------------------------------------------------
// Kernel 2: layer-1 leaky-integrate recurrence; spk1 -> transposed bitmask.
// Strict rn ops, unfused, exact reference op order: ((B*mem)+cur)-reset.
// ---------------------------------------------------------------------------
__global__ void __launch_bounds__(256)
rec1_kernel()
{
    const int warp  = (blockIdx.x * blockDim.x + threadIdx.x) >> 5;
    const int lane  = threadIdx.x & 31;
    const int chunk = warp & 31;
    const int b     = warp >> 5;
    if (b >= BATCH) return;

    const int h = chunk * 32 + lane;
    const bool valid = (h < NHID);

    float mem = 0.f;
#pragma unroll
    for (int t = 0; t < NUM_STEPS; t++) {
        const float c = valid ? g_cur1[((size_t)t * BATCH + b) * NHID + h] : -1.f;
        const float rst = (mem > THRESH) ? THRESH : 0.f;
        mem = __fsub_rn(__fadd_rn(__fmul_rn(BETA, mem), c), rst);
        const uint32_t w = __ballot_sync(0xffffffffu, mem > THRESH);
        if (lane == 0)
            g_maskT[(size_t)chunk * MTOT + (size_t)t * BATCH + b] = w;
    }
}

// ---------------------------------------------------------------------------
// Kernel 3: cur2 = spk1 @ W2^T + b2.  One thread per row, ascending-h chain.
// With spk in {0,1}, rn(spk*w) is exact, so the FMA chain is bit-identical
// to an unfused ascending chain. Zero-skip (fma(0,w,acc)==acc) also exact.
// ---------------------------------------------------------------------------
#define W2LD 12

__global__ void __launch_bounds__(256)
gemm2_kernel(const float* __restrict__ W2, const float* __restrict__ b2)
{
    __shared__ float W2t[1000 * W2LD];   // [h][o], padded
    for (int i = threadIdx.x; i < NOUT * NHID; i += 256) {
        const int o = i / NHID, h = i - o * NHID;
        W2t[h * W2LD + o] = W2[i];
    }
    __syncthreads();

    const int row = blockIdx.x * 256 + threadIdx.x;   // 0..102399

    float acc[NOUT];
#pragma unroll
    for (int o = 0; o < NOUT; o++) acc[o] = 0.f;

#pragma unroll 1
    for (int wd = 0; wd < 32; wd++) {
        const uint32_t w = g_maskT[(size_t)wd * MTOT + row];
        const int nb = (wd < 31) ? 32 : (NHID - 31 * 32);   // 32 or 8
#pragma unroll 8
        for (int bit = 0; bit < nb; bit++) {
            const float f = (float)((w >> bit) & 1u);
            const int h = wd * 32 + bit;
            const float* wrow = &W2t[h * W2LD];
            float4 w0 = *(const float4*)(wrow);
            float4 w1 = *(const float4*)(wrow + 4);
            float2 w2v = *(const float2*)(wrow + 8);
            acc[0] = __fmaf_rn(f, w0.x, acc[0]);
            acc[1] = __fmaf_rn(f, w0.y, acc[1]);
            acc[2] = __fmaf_rn(f, w0.z, acc[2]);
            acc[3] = __fmaf_rn(f, w0.w, acc[3]);
            acc[4] = __fmaf_rn(f, w1.x, acc[4]);
            acc[5] = __fmaf_rn(f, w1.y, acc[5]);
            acc[6] = __fmaf_rn(f, w1.z, acc[6]);
            acc[7] = __fmaf_rn(f, w1.w, acc[7]);
            acc[8] = __fmaf_rn(f, w2v.x, acc[8]);
            acc[9] = __fmaf_rn(f, w2v.y, acc[9]);
        }
    }

    float* out = g_cur2 + (size_t)row * NOUT;
#pragma unroll
    for (int o = 0; o < NOUT; o++)
        out[o] = __fadd_rn(acc[o], __ldg(&b2[o]));
}

// ---------------------------------------------------------------------------
// Kernel 4: layer-2 recurrence + write spk_rec / mem_rec outputs.
// Output layout: [spk_rec (25,4096,10) | mem_rec (25,4096,10)]
// ---------------------------------------------------------------------------
__global__ void __launch_bounds__(256)
rec2_kernel(float* __restrict__ out)
{
    const int idx = blockIdx.x * blockDim.x + threadIdx.x;   // b*10 + o
    if (idx >= BATCH * NOUT) return;

    float mem = 0.f;
#pragma unroll
    for (int t = 0; t < NUM_STEPS; t++) {
        const float c   = g_cur2[(size_t)t * (BATCH * NOUT) + idx];
        const float rst = (mem > THRESH) ? THRESH : 0.f;
        mem = __fsub_rn(__fadd_rn(__fmul_rn(BETA, mem), c), rst);
        const float spk = (mem > THRESH) ? 1.f : 0.f;
        out[(size_t)t * (BATCH * NOUT) + idx] = spk;
        out[(size_t)NUM_STEPS * BATCH * NOUT + (size_t)t * (BATCH * NOUT) + idx] = mem;
    }
}

// ---------------------------------------------------------------------------
extern "C" void kernel_launch(void* const* d_in, const int* in_sizes, int n_in,
                              void* d_out, int out_size)
{
    const float* x  = (const float*)d_in[0];   // [25,4096,784]
    const float* W1 = (const float*)d_in[1];   // [1000,784]
    const float* b1 = (const float*)d_in[2];   // [1000]
    const float* W2 = (const float*)d_in[3];   // [10,1000]
    const float* b2 = (const float*)d_in[4];   // [10]
    float* out = (float*)d_out;

    dim3 g1((NHID + BN - 1) / BN, MTOT / BM);  // (8, 800)
    gemm1_kernel<<<g1, 256>>>(x, W1, b1);

    rec1_kernel<<<(BATCH * 32) / 8, 256>>>();

    gemm2_kernel<<<MTOT / 256, 256>>>(W2, b2);

    rec2_kernel<<<(BATCH * NOUT + 255) / 256, 256>>>(out);
}